// round 2
// baseline (speedup 1.0000x reference)
#include <cuda_runtime.h>

// ---------------------------------------------------------------------------
// GIN 2-layer forward on GB300.
//   h0 = (1+eps1)*x + segsum(x[src] -> dst)
//   h1 = relu(h0 @ W1a + b1a); h2 = relu(h1 @ W1b + b1b)
//   g  = (1+eps2)*h2 + segsum(h2[src] -> dst)
//   h3 = relu(g @ W2a + b2a);  out = h3 @ W2b + b2b
// edge_index dtype is detected at runtime (int32 vs int64) — all in-graph.
// ---------------------------------------------------------------------------

#define N_MAX 100000
#define E_MAX 1600000

// Scratch (static device globals; allocation in kernel_launch is forbidden).
__device__ float g_bufA[(size_t)N_MAX * 512];
__device__ float g_bufB[(size_t)N_MAX * 512];
__device__ int   g_rowptr[N_MAX + 1];
__device__ int   g_colidx[E_MAX];
__device__ int   g_cnt[N_MAX];
__device__ int   g_src[E_MAX];
__device__ int   g_dst[E_MAX];
__device__ int   g_is64;

// --------------------------- dtype detect + decode -------------------------
// If edge_index is really int64 (little-endian, values < 2^31), every odd
// int32 word is zero. Sample 256 odd words; all-zero => int64 layout.

__global__ void k_detect(const int* __restrict__ ei32) {
    __shared__ int nz[256];
    int i = threadIdx.x;
    nz[i] = (ei32[2 * i + 1] != 0) ? 1 : 0;
    __syncthreads();
    for (int off = 128; off > 0; off >>= 1) {
        if (i < off) nz[i] |= nz[i + off];
        __syncthreads();
    }
    if (i == 0) g_is64 = nz[0] ? 0 : 1;
}

__global__ void k_decode(const int* __restrict__ ei32, int E, int n,
                         int* __restrict__ src, int* __restrict__ dst) {
    int e = blockIdx.x * blockDim.x + threadIdx.x;
    if (e >= E) return;
    int s, d;
    if (g_is64) {
        s = ei32[2 * e];
        d = ei32[2 * E + 2 * e];
    } else {
        s = ei32[e];
        d = ei32[E + e];
    }
    // clamp defensively so downstream can never fault
    if (s < 0) s = 0; if (s >= n) s = n - 1;
    if (d < 0) d = 0; if (d >= n) d = n - 1;
    src[e] = s;
    dst[e] = d;
}

// ------------------------------ CSR build ---------------------------------

__global__ void k_zero(int* __restrict__ p, int n) {
    int i = blockIdx.x * blockDim.x + threadIdx.x;
    if (i < n) p[i] = 0;
}

__global__ void k_count(const int* __restrict__ dst, int E, int* __restrict__ cnt) {
    int e = blockIdx.x * blockDim.x + threadIdx.x;
    if (e < E) atomicAdd(&cnt[dst[e]], 1);
}

// Single-block exclusive scan over n counts -> rowptr[0..n]
__global__ void k_scan(const int* __restrict__ cnt, int* __restrict__ rowptr, int n) {
    __shared__ int sums[1024];
    int tid = threadIdx.x;
    int chunk = (n + 1023) >> 10;
    int start = tid * chunk;
    int end = min(start + chunk, n);
    if (start > n) start = n;
    if (end < start) end = start;

    int s = 0;
    for (int i = start; i < end; i++) s += cnt[i];
    sums[tid] = s;
    __syncthreads();

    for (int off = 1; off < 1024; off <<= 1) {
        int v = 0;
        if (tid >= off) v = sums[tid - off];
        __syncthreads();
        if (tid >= off) sums[tid] += v;
        __syncthreads();
    }

    int run = (tid == 0) ? 0 : sums[tid - 1];
    for (int i = start; i < end; i++) {
        rowptr[i] = run;
        run += cnt[i];
    }
    if (end == n) rowptr[n] = run;
}

__global__ void k_scatter(const int* __restrict__ src, const int* __restrict__ dst, int E,
                          const int* __restrict__ rowptr, int* __restrict__ cnt,
                          int* __restrict__ colidx) {
    int e = blockIdx.x * blockDim.x + threadIdx.x;
    if (e < E) {
        int d = dst[e];
        int pos = rowptr[d] + atomicAdd(&cnt[d], 1);
        if (pos >= 0 && pos < E) colidx[pos] = src[e];
    }
}

// ------------------------------ aggregation -------------------------------
// One block per destination node; 256 threads own 1 (F=256) or 2 (F=512)
// feature columns each. Neighbor rows are contiguous -> coalesced loads.

__global__ void k_agg(const float* __restrict__ X, float* __restrict__ Y,
                      const int* __restrict__ rowptr, const int* __restrict__ colidx,
                      const float* __restrict__ epsp, int F) {
    int node = blockIdx.x;
    float scale = 1.0f + epsp[0];
    int c0 = threadIdx.x;
    size_t base = (size_t)node * F;

    float a0 = scale * X[base + c0];
    float a1 = 0.0f;
    if (F == 512) a1 = scale * X[base + c0 + 256];

    int beg = rowptr[node];
    int end = rowptr[node + 1];
    for (int j = beg; j < end; j++) {
        size_t r = (size_t)__ldg(&colidx[j]) * F;
        a0 += __ldg(&X[r + c0]);
        if (F == 512) a1 += __ldg(&X[r + c0 + 256]);
    }
    Y[base + c0] = a0;
    if (F == 512) Y[base + c0 + 256] = a1;
}

// --------------------------------- SGEMM ----------------------------------
// C[M,N] = act(A[M,K] @ B[K,N] + bias), 128x128 tile, BK=8, 8x8 microtile,
// 256 threads. Requires K%8==0, N%128==0 (true: K in {256,512}, N in {512,256}).

template <bool RELU>
__global__ void __launch_bounds__(256)
k_gemm(const float* __restrict__ A, const float* __restrict__ B,
       const float* __restrict__ bias, float* __restrict__ C,
       int M, int K, int N) {
    __shared__ float As[8][128];
    __shared__ float Bs[8][128];

    int tid = threadIdx.x;
    int blockRow = blockIdx.y * 128;
    int blockCol = blockIdx.x * 128;
    int tx = tid & 15;
    int ty = tid >> 4;

    float acc[8][8];
#pragma unroll
    for (int i = 0; i < 8; i++)
#pragma unroll
        for (int j = 0; j < 8; j++) acc[i][j] = 0.0f;

    int arow = tid >> 1;
    int acol = (tid & 1) * 4;
    int brow = tid >> 5;
    int bcol = (tid & 31) * 4;
    bool avalid = (blockRow + arow) < M;
    const float* Aptr = A + (size_t)(blockRow + arow) * K + acol;
    const float* Bptr = B + (size_t)brow * N + blockCol + bcol;

    for (int kt = 0; kt < K; kt += 8) {
        float4 av = make_float4(0.f, 0.f, 0.f, 0.f);
        if (avalid) av = *(const float4*)(Aptr + kt);
        As[acol + 0][arow] = av.x;
        As[acol + 1][arow] = av.y;
        As[acol + 2][arow] = av.z;
        As[acol + 3][arow] = av.w;

        float4 bv = *(const float4*)(Bptr + (size_t)kt * N);
        *(float4*)&Bs[brow][bcol] = bv;
        __syncthreads();

#pragma unroll
        for (int k = 0; k < 8; k++) {
            float4 a0 = *(const float4*)&As[k][ty * 8];
            float4 a1 = *(const float4*)&As[k][ty * 8 + 4];
            float4 b0 = *(const float4*)&Bs[k][tx * 8];
            float4 b1 = *(const float4*)&Bs[k][tx * 8 + 4];
            float ra[8] = {a0.x, a0.y, a0.z, a0.w, a1.x, a1.y, a1.z, a1.w};
            float rb[8] = {b0.x, b0.y, b0.z, b0.w, b1.x, b1.y, b1.z, b1.w};
#pragma unroll
            for (int i = 0; i < 8; i++)
#pragma unroll
                for (int j = 0; j < 8; j++) acc[i][j] = fmaf(ra[i], rb[j], acc[i][j]);
        }
        __syncthreads();
    }

    float bb[8];
#pragma unroll
    for (int j = 0; j < 8; j++) bb[j] = bias[blockCol + tx * 8 + j];

#pragma unroll
    for (int i = 0; i < 8; i++) {
        int row = blockRow + ty * 8 + i;
        if (row >= M) continue;
        float o[8];
#pragma unroll
        for (int j = 0; j < 8; j++) {
            float v = acc[i][j] + bb[j];
            if (RELU) v = fmaxf(v, 0.0f);
            o[j] = v;
        }
        float* cp = C + (size_t)row * N + blockCol + tx * 8;
        *(float4*)(cp + 0) = make_float4(o[0], o[1], o[2], o[3]);
        *(float4*)(cp + 4) = make_float4(o[4], o[5], o[6], o[7]);
    }
}

// ------------------------------ launcher -----------------------------------

extern "C" void kernel_launch(void* const* d_in, const int* in_sizes, int n_in,
                              void* d_out, int out_size) {
    const float* x    = (const float*)d_in[0];
    const int*   ei   = (const int*)d_in[1];
    const float* W1a  = (const float*)d_in[2];
    const float* b1a  = (const float*)d_in[3];
    const float* W1b  = (const float*)d_in[4];
    const float* b1b  = (const float*)d_in[5];
    const float* W2a  = (const float*)d_in[6];
    const float* b2a  = (const float*)d_in[7];
    const float* W2b  = (const float*)d_in[8];
    const float* b2b  = (const float*)d_in[9];
    const float* eps1 = (const float*)d_in[10];
    const float* eps2 = (const float*)d_in[11];
    float*       out  = (float*)d_out;

    int n = in_sizes[0] / 256;  // 100000 nodes
    int E = in_sizes[1] / 2;    // 1600000 edges

    float *bufA, *bufB;
    int *rowptr, *colidx, *cnt, *src, *dst;
    cudaGetSymbolAddress((void**)&bufA, g_bufA);
    cudaGetSymbolAddress((void**)&bufB, g_bufB);
    cudaGetSymbolAddress((void**)&rowptr, g_rowptr);
    cudaGetSymbolAddress((void**)&colidx, g_colidx);
    cudaGetSymbolAddress((void**)&cnt, g_cnt);
    cudaGetSymbolAddress((void**)&src, g_src);
    cudaGetSymbolAddress((void**)&dst, g_dst);

    int zb = (n + 255) / 256;
    int eb = (E + 255) / 256;

    // edge decode (dtype-robust) + CSR build
    k_detect<<<1, 256>>>(ei);
    k_decode<<<eb, 256>>>(ei, E, n, src, dst);
    k_zero<<<zb, 256>>>(cnt, n);
    k_count<<<eb, 256>>>(dst, E, cnt);
    k_scan<<<1, 1024>>>(cnt, rowptr, n);
    k_zero<<<zb, 256>>>(cnt, n);
    k_scatter<<<eb, 256>>>(src, dst, E, rowptr, cnt, colidx);

    // Layer 1
    k_agg<<<n, 256>>>(x, bufA, rowptr, colidx, eps1, 256);
    dim3 g4(512 / 128, (n + 127) / 128);
    k_gemm<true><<<g4, 256>>>(bufA, W1a, b1a, bufB, n, 256, 512);
    k_gemm<true><<<g4, 256>>>(bufB, W1b, b1b, bufA, n, 512, 512);

    // Layer 2
    k_agg<<<n, 256>>>(bufA, bufB, rowptr, colidx, eps2, 512);
    k_gemm<true><<<g4, 256>>>(bufB, W2a, b2a, bufA, n, 512, 512);
    dim3 g2(256 / 128, (n + 127) / 128);
    k_gemm<false><<<g2, 256>>>(bufA, W2b, b2b, out, n, 512, 256);
}

// round 3
// speedup vs baseline: 2.0400x; 2.0400x over previous
#include <cuda_runtime.h>
#include <cstdint>

// ---------------------------------------------------------------------------
// GIN 2-layer forward on GB300 (sm_103a).
// CSR build -> atomic-free aggregation (float4) -> tf32 tensor-core GEMMs
// (mma.sync m16n8k8, RNA-rounded inputs, fused bias+ReLU).
// ---------------------------------------------------------------------------

#define N_MAX 100000
#define E_MAX 1600000

__device__ float g_bufA[(size_t)N_MAX * 512];
__device__ float g_bufB[(size_t)N_MAX * 512];
__device__ int   g_rowptr[N_MAX + 1];
__device__ int   g_colidx[E_MAX];
__device__ int   g_cnt[N_MAX];
__device__ int   g_src[E_MAX];
__device__ int   g_dst[E_MAX];
__device__ int   g_is64;

// --------------------------- dtype detect + decode -------------------------

__global__ void k_detect(const int* __restrict__ ei32) {
    __shared__ int nz[256];
    int i = threadIdx.x;
    nz[i] = (ei32[2 * i + 1] != 0) ? 1 : 0;
    __syncthreads();
    for (int off = 128; off > 0; off >>= 1) {
        if (i < off) nz[i] |= nz[i + off];
        __syncthreads();
    }
    if (i == 0) g_is64 = nz[0] ? 0 : 1;
}

// decode + per-dst count fused
__global__ void k_decode_count(const int* __restrict__ ei32, int E, int n,
                               int* __restrict__ src, int* __restrict__ dst,
                               int* __restrict__ cnt) {
    int e = blockIdx.x * blockDim.x + threadIdx.x;
    if (e >= E) return;
    int s, d;
    if (g_is64) {
        s = ei32[2 * e];
        d = ei32[2 * E + 2 * e];
    } else {
        s = ei32[e];
        d = ei32[E + e];
    }
    if (s < 0) s = 0; if (s >= n) s = n - 1;
    if (d < 0) d = 0; if (d >= n) d = n - 1;
    src[e] = s;
    dst[e] = d;
    atomicAdd(&cnt[d], 1);
}

__global__ void k_zero(int* __restrict__ p, int n) {
    int i = blockIdx.x * blockDim.x + threadIdx.x;
    if (i < n) p[i] = 0;
}

__global__ void k_scan(const int* __restrict__ cnt, int* __restrict__ rowptr, int n) {
    __shared__ int sums[1024];
    int tid = threadIdx.x;
    int chunk = (n + 1023) >> 10;
    int start = min(tid * chunk, n);
    int end = min(start + chunk, n);

    int s = 0;
    for (int i = start; i < end; i++) s += cnt[i];
    sums[tid] = s;
    __syncthreads();

    for (int off = 1; off < 1024; off <<= 1) {
        int v = 0;
        if (tid >= off) v = sums[tid - off];
        __syncthreads();
        if (tid >= off) sums[tid] += v;
        __syncthreads();
    }

    int run = (tid == 0) ? 0 : sums[tid - 1];
    for (int i = start; i < end; i++) {
        rowptr[i] = run;
        run += cnt[i];
    }
    if (end == n) rowptr[n] = run;
}

__global__ void k_scatter(const int* __restrict__ src, const int* __restrict__ dst, int E,
                          const int* __restrict__ rowptr, int* __restrict__ cnt,
                          int* __restrict__ colidx) {
    int e = blockIdx.x * blockDim.x + threadIdx.x;
    if (e < E) {
        int d = dst[e];
        int pos = rowptr[d] + atomicAdd(&cnt[d], 1);
        if (pos >= 0 && pos < E) colidx[pos] = src[e];
    }
}

// ------------------------------ aggregation -------------------------------
// One block per node, blockDim = F/4 threads, float4 gathers, 2 accumulators.

__global__ void k_agg4(const float* __restrict__ X, float* __restrict__ Y,
                       const int* __restrict__ rowptr, const int* __restrict__ colidx,
                       const float* __restrict__ epsp) {
    int node = blockIdx.x;
    int F4 = blockDim.x;
    int t = threadIdx.x;
    float s = 1.0f + epsp[0];
    const float4* Xv = (const float4*)X;
    size_t base = (size_t)node * F4 + t;

    float4 v = Xv[base];
    float4 a0 = make_float4(s * v.x, s * v.y, s * v.z, s * v.w);
    float4 a1 = make_float4(0.f, 0.f, 0.f, 0.f);

    int beg = rowptr[node];
    int end = rowptr[node + 1];
    int j = beg;
    for (; j + 1 < end; j += 2) {
        int r0 = __ldg(&colidx[j]);
        int r1 = __ldg(&colidx[j + 1]);
        float4 u0 = __ldg(&Xv[(size_t)r0 * F4 + t]);
        float4 u1 = __ldg(&Xv[(size_t)r1 * F4 + t]);
        a0.x += u0.x; a0.y += u0.y; a0.z += u0.z; a0.w += u0.w;
        a1.x += u1.x; a1.y += u1.y; a1.z += u1.z; a1.w += u1.w;
    }
    if (j < end) {
        float4 u = __ldg(&Xv[(size_t)__ldg(&colidx[j]) * F4 + t]);
        a0.x += u.x; a0.y += u.y; a0.z += u.z; a0.w += u.w;
    }
    a0.x += a1.x; a0.y += a1.y; a0.z += a1.z; a0.w += a1.w;
    ((float4*)Y)[base] = a0;
}

// ------------------------- tf32 tensor-core GEMM ---------------------------
// C[M,N] = act(A @ B + bias). BM=BN=128, BK=32. 256 threads = 8 warps (2x4),
// warp tile 64x32 = 4x4 m16n8k8 atoms. Double-buffered smem, RNA tf32.

__device__ __forceinline__ uint32_t f2tf32(float f) {
    uint32_t u;
    asm("cvt.rna.tf32.f32 %0, %1;" : "=r"(u) : "f"(f));
    return u;
}

__device__ __forceinline__ void mma_tf32(float c[4], const uint32_t a[4],
                                         const uint32_t b[2]) {
    asm volatile(
        "mma.sync.aligned.m16n8k8.row.col.f32.tf32.tf32.f32 "
        "{%0,%1,%2,%3}, {%4,%5,%6,%7}, {%8,%9}, {%0,%1,%2,%3};"
        : "+f"(c[0]), "+f"(c[1]), "+f"(c[2]), "+f"(c[3])
        : "r"(a[0]), "r"(a[1]), "r"(a[2]), "r"(a[3]), "r"(b[0]), "r"(b[1]));
}

#define SMEM_STRIDE 136
#define SMEM_BUF (32 * SMEM_STRIDE)

template <bool RELU>
__global__ void __launch_bounds__(256)
k_gemm_tf32(const float* __restrict__ A, const float* __restrict__ B,
            const float* __restrict__ bias, float* __restrict__ C,
            int M, int K, int N) {
    extern __shared__ uint32_t smem[];
    uint32_t* sA = smem;                 // 2 buffers of 32 x 136
    uint32_t* sB = smem + 2 * SMEM_BUF;  // 2 buffers of 32 x 136

    const int tid = threadIdx.x;
    const int lane = tid & 31;
    const int w = tid >> 5;
    const int gid = lane >> 2;
    const int tig = lane & 3;
    const int wr = (w >> 2) * 64;   // 0 or 64
    const int wc = (w & 3) * 32;    // 0,32,64,96
    const int blockRow = blockIdx.y * 128;
    const int blockCol = blockIdx.x * 128;

    float c[4][4][4];
#pragma unroll
    for (int i = 0; i < 4; i++)
#pragma unroll
        for (int j = 0; j < 4; j++)
#pragma unroll
            for (int q = 0; q < 4; q++) c[i][j][q] = 0.0f;

    float4 rA[4], rB[4];

    // --- load helpers (inlined by macros of code) ---
    // A: idx = it*256+tid -> row = idx&127, kq = idx>>7 (0..7), elems A[row][kt+4kq..+3]
    // B: idx = it*256+tid -> c4 = idx&31,  k  = idx>>5 (0..31), elems B[kt+k][bc+4c4..+3]

#define LOAD_TILES(KT)                                                        \
    {                                                                         \
        _Pragma("unroll") for (int it = 0; it < 4; it++) {                    \
            int idx = it * 256 + tid;                                         \
            int row = idx & 127, kq = idx >> 7;                               \
            int grow = blockRow + row;                                        \
            rA[it] = make_float4(0.f, 0.f, 0.f, 0.f);                         \
            if (grow < M)                                                     \
                rA[it] = *(const float4*)&A[(size_t)grow * K + (KT) + kq * 4];\
        }                                                                     \
        _Pragma("unroll") for (int it = 0; it < 4; it++) {                    \
            int idx = it * 256 + tid;                                         \
            int c4 = idx & 31, k = idx >> 5;                                  \
            rB[it] = *(const float4*)&B[(size_t)((KT) + k) * N + blockCol + c4 * 4];\
        }                                                                     \
    }

#define STORE_TILES(BUF)                                                      \
    {                                                                         \
        uint32_t* pa = sA + (BUF) * SMEM_BUF;                                 \
        uint32_t* pb = sB + (BUF) * SMEM_BUF;                                 \
        _Pragma("unroll") for (int it = 0; it < 4; it++) {                    \
            int idx = it * 256 + tid;                                         \
            int row = idx & 127, kq = idx >> 7;                               \
            pa[(kq * 4 + 0) * SMEM_STRIDE + row] = f2tf32(rA[it].x);          \
            pa[(kq * 4 + 1) * SMEM_STRIDE + row] = f2tf32(rA[it].y);          \
            pa[(kq * 4 + 2) * SMEM_STRIDE + row] = f2tf32(rA[it].z);          \
            pa[(kq * 4 + 3) * SMEM_STRIDE + row] = f2tf32(rA[it].w);          \
        }                                                                     \
        _Pragma("unroll") for (int it = 0; it < 4; it++) {                    \
            int idx = it * 256 + tid;                                         \
            int c4 = idx & 31, k = idx >> 5;                                  \
            pb[k * SMEM_STRIDE + c4 * 4 + 0] = f2tf32(rB[it].x);              \
            pb[k * SMEM_STRIDE + c4 * 4 + 1] = f2tf32(rB[it].y);              \
            pb[k * SMEM_STRIDE + c4 * 4 + 2] = f2tf32(rB[it].z);              \
            pb[k * SMEM_STRIDE + c4 * 4 + 3] = f2tf32(rB[it].w);              \
        }                                                                     \
    }

    LOAD_TILES(0);
    STORE_TILES(0);
    __syncthreads();

    int buf = 0;
    for (int kt = 0; kt < K; kt += 32) {
        bool has_next = (kt + 32) < K;
        if (has_next) LOAD_TILES(kt + 32);

        const uint32_t* pa = sA + buf * SMEM_BUF;
        const uint32_t* pb = sB + buf * SMEM_BUF;
#pragma unroll
        for (int ks = 0; ks < 4; ks++) {
            int kb = ks * 8;
            uint32_t a[4][4], b[4][2];
#pragma unroll
            for (int i = 0; i < 4; i++) {
                int m0 = wr + i * 16 + gid;
                a[i][0] = pa[(kb + tig) * SMEM_STRIDE + m0];
                a[i][1] = pa[(kb + tig) * SMEM_STRIDE + m0 + 8];
                a[i][2] = pa[(kb + tig + 4) * SMEM_STRIDE + m0];
                a[i][3] = pa[(kb + tig + 4) * SMEM_STRIDE + m0 + 8];
            }
#pragma unroll
            for (int j = 0; j < 4; j++) {
                int n0 = wc + j * 8 + gid;
                b[j][0] = pb[(kb + tig) * SMEM_STRIDE + n0];
                b[j][1] = pb[(kb + tig + 4) * SMEM_STRIDE + n0];
            }
#pragma unroll
            for (int i = 0; i < 4; i++)
#pragma unroll
                for (int j = 0; j < 4; j++) mma_tf32(c[i][j], a[i], b[j]);
        }

        if (has_next) {
            STORE_TILES(buf ^ 1);
            __syncthreads();
            buf ^= 1;
        }
    }

    // epilogue: bias + optional relu, float2 stores
#pragma unroll
    for (int j = 0; j < 4; j++) {
        int n0 = blockCol + wc + j * 8 + 2 * tig;
        float bb0 = bias[n0];
        float bb1 = bias[n0 + 1];
#pragma unroll
        for (int i = 0; i < 4; i++) {
            int m = blockRow + wr + i * 16 + gid;
            if (m < M) {
                float v0 = c[i][j][0] + bb0;
                float v1 = c[i][j][1] + bb1;
                if (RELU) { v0 = fmaxf(v0, 0.f); v1 = fmaxf(v1, 0.f); }
                *(float2*)&C[(size_t)m * N + n0] = make_float2(v0, v1);
            }
            if (m + 8 < M) {
                float v2 = c[i][j][2] + bb0;
                float v3 = c[i][j][3] + bb1;
                if (RELU) { v2 = fmaxf(v2, 0.f); v3 = fmaxf(v3, 0.f); }
                *(float2*)&C[(size_t)(m + 8) * N + n0] = make_float2(v2, v3);
            }
        }
    }
#undef LOAD_TILES
#undef STORE_TILES
}

// ------------------------------ launcher -----------------------------------

extern "C" void kernel_launch(void* const* d_in, const int* in_sizes, int n_in,
                              void* d_out, int out_size) {
    const float* x    = (const float*)d_in[0];
    const int*   ei   = (const int*)d_in[1];
    const float* W1a  = (const float*)d_in[2];
    const float* b1a  = (const float*)d_in[3];
    const float* W1b  = (const float*)d_in[4];
    const float* b1b  = (const float*)d_in[5];
    const float* W2a  = (const float*)d_in[6];
    const float* b2a  = (const float*)d_in[7];
    const float* W2b  = (const float*)d_in[8];
    const float* b2b  = (const float*)d_in[9];
    const float* eps1 = (const float*)d_in[10];
    const float* eps2 = (const float*)d_in[11];
    float*       out  = (float*)d_out;

    int n = in_sizes[0] / 256;  // 100000 nodes
    int E = in_sizes[1] / 2;    // 1600000 edges

    float *bufA, *bufB;
    int *rowptr, *colidx, *cnt, *src, *dst;
    cudaGetSymbolAddress((void**)&bufA, g_bufA);
    cudaGetSymbolAddress((void**)&bufB, g_bufB);
    cudaGetSymbolAddress((void**)&rowptr, g_rowptr);
    cudaGetSymbolAddress((void**)&colidx, g_colidx);
    cudaGetSymbolAddress((void**)&cnt, g_cnt);
    cudaGetSymbolAddress((void**)&src, g_src);
    cudaGetSymbolAddress((void**)&dst, g_dst);

    const int smem_bytes = 4 * SMEM_BUF * sizeof(uint32_t);  // 69632
    cudaFuncSetAttribute(k_gemm_tf32<true>,
                         cudaFuncAttributeMaxDynamicSharedMemorySize, smem_bytes);
    cudaFuncSetAttribute(k_gemm_tf32<false>,
                         cudaFuncAttributeMaxDynamicSharedMemorySize, smem_bytes);

    int zb = (n + 255) / 256;
    int eb = (E + 255) / 256;

    // edge decode (dtype-robust) + CSR build
    k_detect<<<1, 256>>>(ei);
    k_zero<<<zb, 256>>>(cnt, n);
    k_decode_count<<<eb, 256>>>(ei, E, n, src, dst, cnt);
    k_scan<<<1, 1024>>>(cnt, rowptr, n);
    k_zero<<<zb, 256>>>(cnt, n);
    k_scatter<<<eb, 256>>>(src, dst, E, rowptr, cnt, colidx);

    int mtiles = (n + 127) / 128;

    // Layer 1
    k_agg4<<<n, 64>>>(x, bufA, rowptr, colidx, eps1);          // F=256
    dim3 g4(4, mtiles);  // N=512
    k_gemm_tf32<true><<<g4, 256, smem_bytes>>>(bufA, W1a, b1a, bufB, n, 256, 512);
    k_gemm_tf32<true><<<g4, 256, smem_bytes>>>(bufB, W1b, b1b, bufA, n, 512, 512);

    // Layer 2
    k_agg4<<<n, 128>>>(bufA, bufB, rowptr, colidx, eps2);      // F=512
    k_gemm_tf32<true><<<g4, 256, smem_bytes>>>(bufB, W2a, b2a, bufA, n, 512, 512);
    dim3 g2(2, mtiles);  // N=256
    k_gemm_tf32<false><<<g2, 256, smem_bytes>>>(bufA, W2b, b2b, out, n, 512, 256);
}

// round 5
// speedup vs baseline: 3.0783x; 1.5090x over previous
#include <cuda_runtime.h>
#include <cstdint>

// ---------------------------------------------------------------------------
// GIN 2-layer forward on GB300 (sm_103 target - no tcgen05 available).
// CSR build (parallel scan) -> atomic-free float4 aggregation ->
// tf32 mma.sync GEMMs with cp.async double-buffered pipeline,
// pre-rounded tf32 operands (no in-loop cvt), fused bias+ReLU.
// ---------------------------------------------------------------------------

#define N_MAX 100000
#define E_MAX 1600000

__device__ float g_bufA[(size_t)N_MAX * 512];
__device__ float g_bufB[(size_t)N_MAX * 512];
__device__ int   g_rowptr[N_MAX + 1];
__device__ int   g_colidx[E_MAX];
__device__ int   g_cnt[N_MAX];
__device__ int   g_src[E_MAX];
__device__ int   g_dst[E_MAX];
__device__ int   g_bsum[128];
__device__ int   g_is64;
// tf32(RNA)-rounded weights, same [K,N] layout as inputs
__device__ float g_w1a[256 * 512];
__device__ float g_w1b[512 * 512];
__device__ float g_w2a[512 * 512];
__device__ float g_w2b[512 * 256];

// ------------------------------- helpers -----------------------------------

__device__ __forceinline__ uint32_t smem_u32(const void* p) {
    uint32_t a;
    asm("{ .reg .u64 t; cvta.to.shared.u64 t, %1; cvt.u32.u64 %0, t; }"
        : "=r"(a) : "l"(p));
    return a;
}
__device__ __forceinline__ float rna_tf32(float f) {
    uint32_t u;
    asm("cvt.rna.tf32.f32 %0, %1;" : "=r"(u) : "f"(f));
    return __uint_as_float(u);
}
__device__ __forceinline__ void cp16(uint32_t dst, const void* src, int srcsize) {
    asm volatile("cp.async.cg.shared.global [%0], [%1], 16, %2;"
                 :: "r"(dst), "l"(src), "r"(srcsize) : "memory");
}
#define CP_COMMIT() asm volatile("cp.async.commit_group;" ::: "memory")
#define CP_WAIT(n)  asm volatile("cp.async.wait_group %0;" :: "n"(n) : "memory")

__device__ __forceinline__ void mma_tf32(float c[4], const uint32_t a[4],
                                         const uint32_t b[2]) {
    asm volatile(
        "mma.sync.aligned.m16n8k8.row.col.f32.tf32.tf32.f32 "
        "{%0,%1,%2,%3}, {%4,%5,%6,%7}, {%8,%9}, {%0,%1,%2,%3};"
        : "+f"(c[0]), "+f"(c[1]), "+f"(c[2]), "+f"(c[3])
        : "r"(a[0]), "r"(a[1]), "r"(a[2]), "r"(a[3]), "r"(b[0]), "r"(b[1]));
}

// --------------------------- dtype detect + decode -------------------------

__global__ void k_detect(const int* __restrict__ ei32) {
    __shared__ int nz[256];
    int i = threadIdx.x;
    nz[i] = (ei32[2 * i + 1] != 0) ? 1 : 0;
    __syncthreads();
    for (int off = 128; off > 0; off >>= 1) {
        if (i < off) nz[i] |= nz[i + off];
        __syncthreads();
    }
    if (i == 0) g_is64 = nz[0] ? 0 : 1;
}

__global__ void k_decode_count(const int* __restrict__ ei32, int E, int n,
                               int* __restrict__ src, int* __restrict__ dst,
                               int* __restrict__ cnt) {
    int e = blockIdx.x * blockDim.x + threadIdx.x;
    if (e >= E) return;
    int s, d;
    if (g_is64) {
        s = ei32[2 * e];
        d = ei32[2 * E + 2 * e];
    } else {
        s = ei32[e];
        d = ei32[E + e];
    }
    if (s < 0) s = 0; if (s >= n) s = n - 1;
    if (d < 0) d = 0; if (d >= n) d = n - 1;
    src[e] = s;
    dst[e] = d;
    atomicAdd(&cnt[d], 1);
}

__global__ void k_zero(int* __restrict__ p, int n) {
    int i = blockIdx.x * blockDim.x + threadIdx.x;
    if (i < n) p[i] = 0;
}

// --------------------------- parallel scan (3 kernels) ---------------------

__global__ void k_bsum(const int* __restrict__ cnt, int n, int* __restrict__ bsum) {
    __shared__ int sh[256];
    int b = blockIdx.x, t = threadIdx.x;
    int base = b * 1024;
    int s = 0;
#pragma unroll
    for (int q = 0; q < 4; q++) {
        int idx = base + q * 256 + t;
        if (idx < n) s += cnt[idx];
    }
    sh[t] = s;
    __syncthreads();
    for (int off = 128; off > 0; off >>= 1) {
        if (t < off) sh[t] += sh[t + off];
        __syncthreads();
    }
    if (t == 0) bsum[b] = sh[0];
}

__global__ void k_btop(int* __restrict__ bsum, int nb, int* __restrict__ rowptr, int n) {
    __shared__ int sh[128];
    int t = threadIdx.x;
    int v = (t < nb) ? bsum[t] : 0;
    sh[t] = v;
    __syncthreads();
    for (int off = 1; off < 128; off <<= 1) {
        int u = 0;
        if (t >= off) u = sh[t - off];
        __syncthreads();
        if (t >= off) sh[t] += u;
        __syncthreads();
    }
    if (t < nb) bsum[t] = sh[t] - v;  // exclusive
    if (t == 127) rowptr[n] = sh[127];
}

__global__ void k_scanw(const int* __restrict__ cnt, int n,
                        const int* __restrict__ bsum, int* __restrict__ rowptr) {
    __shared__ int sh[256];
    int b = blockIdx.x, t = threadIdx.x;
    int base = b * 1024 + t * 4;
    int v[4];
#pragma unroll
    for (int q = 0; q < 4; q++) v[q] = (base + q < n) ? cnt[base + q] : 0;
    int ts = v[0] + v[1] + v[2] + v[3];
    sh[t] = ts;
    __syncthreads();
    for (int off = 1; off < 256; off <<= 1) {
        int u = 0;
        if (t >= off) u = sh[t - off];
        __syncthreads();
        if (t >= off) sh[t] += u;
        __syncthreads();
    }
    int run = sh[t] - ts + bsum[b];
#pragma unroll
    for (int q = 0; q < 4; q++) {
        if (base + q < n) rowptr[base + q] = run;
        run += v[q];
    }
}

__global__ void k_scatter(const int* __restrict__ src, const int* __restrict__ dst, int E,
                          const int* __restrict__ rowptr, int* __restrict__ cnt,
                          int* __restrict__ colidx) {
    int e = blockIdx.x * blockDim.x + threadIdx.x;
    if (e < E) {
        int d = dst[e];
        int pos = rowptr[d] + atomicAdd(&cnt[d], 1);
        if (pos >= 0 && pos < E) colidx[pos] = src[e];
    }
}

// ------------------------------ aggregation -------------------------------
// One block per node, blockDim = F/4 threads, float4 gathers, 2 accumulators.
// Output RNA-rounded to tf32 (feeds tensor-core GEMM).

__global__ void k_agg4(const float* __restrict__ X, float* __restrict__ Y,
                       const int* __restrict__ rowptr, const int* __restrict__ colidx,
                       const float* __restrict__ epsp) {
    int node = blockIdx.x;
    int F4 = blockDim.x;
    int t = threadIdx.x;
    float s = 1.0f + epsp[0];
    const float4* Xv = (const float4*)X;
    size_t base = (size_t)node * F4 + t;

    float4 v = Xv[base];
    float4 a0 = make_float4(s * v.x, s * v.y, s * v.z, s * v.w);
    float4 a1 = make_float4(0.f, 0.f, 0.f, 0.f);

    int beg = rowptr[node];
    int end = rowptr[node + 1];
    int j = beg;
    for (; j + 1 < end; j += 2) {
        int r0 = __ldg(&colidx[j]);
        int r1 = __ldg(&colidx[j + 1]);
        float4 u0 = __ldg(&Xv[(size_t)r0 * F4 + t]);
        float4 u1 = __ldg(&Xv[(size_t)r1 * F4 + t]);
        a0.x += u0.x; a0.y += u0.y; a0.z += u0.z; a0.w += u0.w;
        a1.x += u1.x; a1.y += u1.y; a1.z += u1.z; a1.w += u1.w;
    }
    if (j < end) {
        float4 u = __ldg(&Xv[(size_t)__ldg(&colidx[j]) * F4 + t]);
        a0.x += u.x; a0.y += u.y; a0.z += u.z; a0.w += u.w;
    }
    a0.x = rna_tf32(a0.x + a1.x);
    a0.y = rna_tf32(a0.y + a1.y);
    a0.z = rna_tf32(a0.z + a1.z);
    a0.w = rna_tf32(a0.w + a1.w);
    ((float4*)Y)[base] = a0;
}

// --------------------------- weight tf32 rounding --------------------------

__global__ void k_round4(const float* __restrict__ W, float* __restrict__ Wo, int n4) {
    int i = blockIdx.x * blockDim.x + threadIdx.x;
    if (i < n4) {
        float4 v = ((const float4*)W)[i];
        v.x = rna_tf32(v.x); v.y = rna_tf32(v.y);
        v.z = rna_tf32(v.z); v.w = rna_tf32(v.w);
        ((float4*)Wo)[i] = v;
    }
}

// ------------------------- tf32 mma.sync GEMM (v2) --------------------------
// C[M,N] = act(A[M,K] @ B[K,N] + bias). BM=BN=128, BK=32, 256 thr = 8 warps,
// warp tile 64x32 (4x4 m16n8k8). cp.async double buffer, pre-rounded tf32.
// smem A: [m][k], stride 36 floats (fragment bank = 4*gid+tig, conflict-free)
// smem B: [k][n], stride 136 floats (fragment bank = 8*tig+gid, conflict-free)

#define ASTR 36
#define BSTR 136
#define ABUF_B (128 * ASTR * 4)   // 18432 bytes
#define BBUF_B (32 * BSTR * 4)    // 17408 bytes
#define GSM_BYTES (2 * (ABUF_B + BBUF_B))  // 71680

template <bool RELU, bool ROUND>
__global__ void __launch_bounds__(256)
k_gemm_tf32(const float* __restrict__ A, const float* __restrict__ B,
            const float* __restrict__ bias, float* __restrict__ C,
            int M, int K, int N) {
    extern __shared__ __align__(16) char smem[];
    const uint32_t sb = smem_u32(smem);
    const uint32_t sA[2] = {sb, sb + ABUF_B};
    const uint32_t sB[2] = {sb + 2 * ABUF_B, sb + 2 * ABUF_B + BBUF_B};

    const int tid = threadIdx.x;
    const int lane = tid & 31;
    const int w = tid >> 5;
    const int gid = lane >> 2;
    const int tig = lane & 3;
    const int wr = (w >> 2) * 64;
    const int wc = (w & 3) * 32;
    const int blockRow = blockIdx.y * 128;
    const int blockCol = blockIdx.x * 128;
    const int nch = K >> 5;

    float c[4][4][4];
#pragma unroll
    for (int i = 0; i < 4; i++)
#pragma unroll
        for (int j = 0; j < 4; j++)
#pragma unroll
            for (int q = 0; q < 4; q++) c[i][j][q] = 0.0f;

    // cp.async one K-chunk (32 wide) into buffer bf
#define ISSUE(KT, bf)                                                          \
    {                                                                          \
        _Pragma("unroll") for (int t = 0; t < 4; t++) {                        \
            int cidx = tid + t * 256;                                          \
            int row = cidx >> 3, q = cidx & 7;                                 \
            int grow = blockRow + row;                                         \
            cp16(sA[bf] + (row * ASTR + q * 4) * 4,                            \
                 &A[(size_t)grow * K + (KT) + q * 4], grow < M ? 16 : 0);      \
        }                                                                      \
        _Pragma("unroll") for (int t = 0; t < 4; t++) {                        \
            int cidx = tid + t * 256;                                          \
            int k = cidx >> 5, q = cidx & 31;                                  \
            cp16(sB[bf] + (k * BSTR + q * 4) * 4,                              \
                 &B[(size_t)((KT) + k) * N + blockCol + q * 4], 16);           \
        }                                                                      \
        CP_COMMIT();                                                           \
    }

    ISSUE(0, 0);

    for (int i = 0; i < nch; i++) {
        int bf = i & 1;
        if (i + 1 < nch) {
            ISSUE((i + 1) << 5, bf ^ 1);
            CP_WAIT(1);
        } else {
            CP_WAIT(0);
        }
        __syncthreads();

        const uint32_t* pa = (const uint32_t*)(smem + (sA[bf] - sb));
        const uint32_t* pb = (const uint32_t*)(smem + (sB[bf] - sb));
#pragma unroll
        for (int ks = 0; ks < 4; ks++) {
            int kb = ks * 8;
            uint32_t a[4][4], b[4][2];
#pragma unroll
            for (int ii = 0; ii < 4; ii++) {
                int m0 = wr + ii * 16 + gid;
                a[ii][0] = pa[m0 * ASTR + kb + tig];
                a[ii][1] = pa[(m0 + 8) * ASTR + kb + tig];
                a[ii][2] = pa[m0 * ASTR + kb + tig + 4];
                a[ii][3] = pa[(m0 + 8) * ASTR + kb + tig + 4];
            }
#pragma unroll
            for (int j = 0; j < 4; j++) {
                int n0 = wc + j * 8 + gid;
                b[j][0] = pb[(kb + tig) * BSTR + n0];
                b[j][1] = pb[(kb + tig + 4) * BSTR + n0];
            }
#pragma unroll
            for (int ii = 0; ii < 4; ii++)
#pragma unroll
                for (int j = 0; j < 4; j++) mma_tf32(c[ii][j], a[ii], b[j]);
        }
        __syncthreads();  // WAR: done reading bf before next issue overwrites it
    }

    // epilogue: bias + relu (+ tf32 round), float2 stores
#pragma unroll
    for (int j = 0; j < 4; j++) {
        int n0 = blockCol + wc + j * 8 + 2 * tig;
        float bb0 = bias[n0];
        float bb1 = bias[n0 + 1];
#pragma unroll
        for (int i = 0; i < 4; i++) {
            int m = blockRow + wr + i * 16 + gid;
            if (m < M) {
                float v0 = c[i][j][0] + bb0;
                float v1 = c[i][j][1] + bb1;
                if (RELU) { v0 = fmaxf(v0, 0.f); v1 = fmaxf(v1, 0.f); }
                if (ROUND) { v0 = rna_tf32(v0); v1 = rna_tf32(v1); }
                *(float2*)&C[(size_t)m * N + n0] = make_float2(v0, v1);
            }
            if (m + 8 < M) {
                float v2 = c[i][j][2] + bb0;
                float v3 = c[i][j][3] + bb1;
                if (RELU) { v2 = fmaxf(v2, 0.f); v3 = fmaxf(v3, 0.f); }
                if (ROUND) { v2 = rna_tf32(v2); v3 = rna_tf32(v3); }
                *(float2*)&C[(size_t)(m + 8) * N + n0] = make_float2(v2, v3);
            }
        }
    }
#undef ISSUE
}

// ------------------------------ launcher -----------------------------------

extern "C" void kernel_launch(void* const* d_in, const int* in_sizes, int n_in,
                              void* d_out, int out_size) {
    const float* x    = (const float*)d_in[0];
    const int*   ei   = (const int*)d_in[1];
    const float* W1a  = (const float*)d_in[2];
    const float* b1a  = (const float*)d_in[3];
    const float* W1b  = (const float*)d_in[4];
    const float* b1b  = (const float*)d_in[5];
    const float* W2a  = (const float*)d_in[6];
    const float* b2a  = (const float*)d_in[7];
    const float* W2b  = (const float*)d_in[8];
    const float* b2b  = (const float*)d_in[9];
    const float* eps1 = (const float*)d_in[10];
    const float* eps2 = (const float*)d_in[11];
    float*       out  = (float*)d_out;

    int n = in_sizes[0] / 256;  // 100000 nodes
    int E = in_sizes[1] / 2;    // 1600000 edges

    float *bufA, *bufB, *w1a, *w1b, *w2a, *w2b;
    int *rowptr, *colidx, *cnt, *src, *dst, *bsum;
    cudaGetSymbolAddress((void**)&bufA, g_bufA);
    cudaGetSymbolAddress((void**)&bufB, g_bufB);
    cudaGetSymbolAddress((void**)&rowptr, g_rowptr);
    cudaGetSymbolAddress((void**)&colidx, g_colidx);
    cudaGetSymbolAddress((void**)&cnt, g_cnt);
    cudaGetSymbolAddress((void**)&src, g_src);
    cudaGetSymbolAddress((void**)&dst, g_dst);
    cudaGetSymbolAddress((void**)&bsum, g_bsum);
    cudaGetSymbolAddress((void**)&w1a, g_w1a);
    cudaGetSymbolAddress((void**)&w1b, g_w1b);
    cudaGetSymbolAddress((void**)&w2a, g_w2a);
    cudaGetSymbolAddress((void**)&w2b, g_w2b);

    cudaFuncSetAttribute(k_gemm_tf32<true, true>,
                         cudaFuncAttributeMaxDynamicSharedMemorySize, GSM_BYTES);
    cudaFuncSetAttribute(k_gemm_tf32<false, false>,
                         cudaFuncAttributeMaxDynamicSharedMemorySize, GSM_BYTES);

    int zb = (n + 255) / 256;
    int eb = (E + 255) / 256;
    int nb = (n + 1023) / 1024;

    // weight rounding (tf32 RNA, layout unchanged)
    k_round4<<<(256 * 512 / 4 + 255) / 256, 256>>>(W1a, w1a, 256 * 512 / 4);
    k_round4<<<(512 * 512 / 4 + 255) / 256, 256>>>(W1b, w1b, 512 * 512 / 4);
    k_round4<<<(512 * 512 / 4 + 255) / 256, 256>>>(W2a, w2a, 512 * 512 / 4);
    k_round4<<<(512 * 256 / 4 + 255) / 256, 256>>>(W2b, w2b, 512 * 256 / 4);

    // edge decode (dtype-robust) + CSR build
    k_detect<<<1, 256>>>(ei);
    k_zero<<<zb, 256>>>(cnt, n);
    k_decode_count<<<eb, 256>>>(ei, E, n, src, dst, cnt);
    k_bsum<<<nb, 256>>>(cnt, n, bsum);
    k_btop<<<1, 128>>>(bsum, nb, rowptr, n);
    k_scanw<<<nb, 256>>>(cnt, n, bsum, rowptr);
    k_zero<<<zb, 256>>>(cnt, n);
    k_scatter<<<eb, 256>>>(src, dst, E, rowptr, cnt, colidx);

    int mtiles = (n + 127) / 128;

    // Layer 1
    k_agg4<<<n, 64>>>(x, bufA, rowptr, colidx, eps1);          // F=256
    dim3 g4(4, mtiles);
    k_gemm_tf32<true, true><<<g4, 256, GSM_BYTES>>>(bufA, w1a, b1a, bufB, n, 256, 512);
    k_gemm_tf32<true, true><<<g4, 256, GSM_BYTES>>>(bufB, w1b, b1b, bufA, n, 512, 512);

    // Layer 2
    k_agg4<<<n, 128>>>(bufA, bufB, rowptr, colidx, eps2);      // F=512
    k_gemm_tf32<true, true><<<g4, 256, GSM_BYTES>>>(bufB, w2a, b2a, bufA, n, 512, 512);
    dim3 g2(2, mtiles);
    k_gemm_tf32<false, false><<<g2, 256, GSM_BYTES>>>(bufA, w2b, b2b, out, n, 512, 256);
}

// round 6
// speedup vs baseline: 5.1745x; 1.6810x over previous
#include <cuda_runtime.h>
#include <cuda_fp16.h>
#include <cstdint>

// ---------------------------------------------------------------------------
// GIN 2-layer forward on GB300 (sm_103 target - no tcgen05 in toolchain).
// CSR build (parallel scan) -> warp-per-node fp16 gather aggregation (fp32
// accum) -> fp16 mma.sync m16n8k16 GEMMs (3-stage cp.async, BK=64,
// fused bias+ReLU). All intermediates stored fp16 (same 10 mantissa bits as
// tf32); final output fp32.
// ---------------------------------------------------------------------------

#define N_MAX 100000
#define E_MAX 1600000

__device__ int    g_rowptr[N_MAX + 1];
__device__ int    g_colidx[E_MAX];
__device__ int    g_cnt[N_MAX];
__device__ int    g_src[E_MAX];
__device__ int    g_dst[E_MAX];
__device__ int    g_bsum[128];
__device__ int    g_is64;
__device__ __half g_xh[(size_t)N_MAX * 256];
__device__ __half g_h0[(size_t)N_MAX * 256];
__device__ __half g_h1[(size_t)N_MAX * 512];
__device__ __half g_h2[(size_t)N_MAX * 512];
__device__ __half g_g2[(size_t)N_MAX * 512];
// weights transposed to [N][K], fp16
__device__ __half g_w1a[512 * 256];
__device__ __half g_w1b[512 * 512];
__device__ __half g_w2a[512 * 512];
__device__ __half g_w2b[256 * 512];

// ------------------------------- helpers -----------------------------------

__device__ __forceinline__ uint32_t smem_u32(const void* p) {
    uint32_t a;
    asm("{ .reg .u64 t; cvta.to.shared.u64 t, %1; cvt.u32.u64 %0, t; }"
        : "=r"(a) : "l"(p));
    return a;
}
__device__ __forceinline__ void cp16(uint32_t dst, const void* src, int srcsize) {
    asm volatile("cp.async.cg.shared.global [%0], [%1], 16, %2;"
                 :: "r"(dst), "l"(src), "r"(srcsize) : "memory");
}
#define CP_COMMIT() asm volatile("cp.async.commit_group;" ::: "memory")
#define CP_WAIT(n)  asm volatile("cp.async.wait_group %0;" :: "n"(n) : "memory")

__device__ __forceinline__ void mma_f16(float c[4], const uint32_t a[4],
                                        const uint32_t b[2]) {
    asm volatile(
        "mma.sync.aligned.m16n8k16.row.col.f32.f16.f16.f32 "
        "{%0,%1,%2,%3}, {%4,%5,%6,%7}, {%8,%9}, {%0,%1,%2,%3};"
        : "+f"(c[0]), "+f"(c[1]), "+f"(c[2]), "+f"(c[3])
        : "r"(a[0]), "r"(a[1]), "r"(a[2]), "r"(a[3]), "r"(b[0]), "r"(b[1]));
}

// --------------------------- dtype detect + decode -------------------------

__global__ void k_detect(const int* __restrict__ ei32) {
    __shared__ int nz[256];
    int i = threadIdx.x;
    nz[i] = (ei32[2 * i + 1] != 0) ? 1 : 0;
    __syncthreads();
    for (int off = 128; off > 0; off >>= 1) {
        if (i < off) nz[i] |= nz[i + off];
        __syncthreads();
    }
    if (i == 0) g_is64 = nz[0] ? 0 : 1;
}

__global__ void k_decode_count(const int* __restrict__ ei32, int E, int n,
                               int* __restrict__ src, int* __restrict__ dst,
                               int* __restrict__ cnt) {
    int e = blockIdx.x * blockDim.x + threadIdx.x;
    if (e >= E) return;
    int s, d;
    if (g_is64) {
        s = ei32[2 * e];
        d = ei32[2 * E + 2 * e];
    } else {
        s = ei32[e];
        d = ei32[E + e];
    }
    if (s < 0) s = 0; if (s >= n) s = n - 1;
    if (d < 0) d = 0; if (d >= n) d = n - 1;
    src[e] = s;
    dst[e] = d;
    atomicAdd(&cnt[d], 1);
}

__global__ void k_zero(int* __restrict__ p, int n) {
    int i = blockIdx.x * blockDim.x + threadIdx.x;
    if (i < n) p[i] = 0;
}

// --------------------------- parallel scan (3 kernels) ---------------------

__global__ void k_bsum(const int* __restrict__ cnt, int n, int* __restrict__ bsum) {
    __shared__ int sh[256];
    int b = blockIdx.x, t = threadIdx.x;
    int base = b * 1024;
    int s = 0;
#pragma unroll
    for (int q = 0; q < 4; q++) {
        int idx = base + q * 256 + t;
        if (idx < n) s += cnt[idx];
    }
    sh[t] = s;
    __syncthreads();
    for (int off = 128; off > 0; off >>= 1) {
        if (t < off) sh[t] += sh[t + off];
        __syncthreads();
    }
    if (t == 0) bsum[b] = sh[0];
}

__global__ void k_btop(int* __restrict__ bsum, int nb, int* __restrict__ rowptr, int n) {
    __shared__ int sh[128];
    int t = threadIdx.x;
    int v = (t < nb) ? bsum[t] : 0;
    sh[t] = v;
    __syncthreads();
    for (int off = 1; off < 128; off <<= 1) {
        int u = 0;
        if (t >= off) u = sh[t - off];
        __syncthreads();
        if (t >= off) sh[t] += u;
        __syncthreads();
    }
    if (t < nb) bsum[t] = sh[t] - v;
    if (t == 127) rowptr[n] = sh[127];
}

__global__ void k_scanw(const int* __restrict__ cnt, int n,
                        const int* __restrict__ bsum, int* __restrict__ rowptr) {
    __shared__ int sh[256];
    int b = blockIdx.x, t = threadIdx.x;
    int base = b * 1024 + t * 4;
    int v[4];
#pragma unroll
    for (int q = 0; q < 4; q++) v[q] = (base + q < n) ? cnt[base + q] : 0;
    int ts = v[0] + v[1] + v[2] + v[3];
    sh[t] = ts;
    __syncthreads();
    for (int off = 1; off < 256; off <<= 1) {
        int u = 0;
        if (t >= off) u = sh[t - off];
        __syncthreads();
        if (t >= off) sh[t] += u;
        __syncthreads();
    }
    int run = sh[t] - ts + bsum[b];
#pragma unroll
    for (int q = 0; q < 4; q++) {
        if (base + q < n) rowptr[base + q] = run;
        run += v[q];
    }
}

__global__ void k_scatter(const int* __restrict__ src, const int* __restrict__ dst, int E,
                          const int* __restrict__ rowptr, int* __restrict__ cnt,
                          int* __restrict__ colidx) {
    int e = blockIdx.x * blockDim.x + threadIdx.x;
    if (e < E) {
        int d = dst[e];
        int pos = rowptr[d] + atomicAdd(&cnt[d], 1);
        if (pos >= 0 && pos < E) colidx[pos] = src[e];
    }
}

// ------------------------------- conversions -------------------------------

__global__ void k_cvt_h(const float4* __restrict__ X, __half2* __restrict__ Y, int n4) {
    int i = blockIdx.x * blockDim.x + threadIdx.x;
    if (i < n4) {
        float4 v = X[i];
        Y[2 * i] = __floats2half2_rn(v.x, v.y);
        Y[2 * i + 1] = __floats2half2_rn(v.z, v.w);
    }
}

// W [K,N] fp32 -> Wt [N,K] fp16
__global__ void k_wt_h(const float* __restrict__ W, __half* __restrict__ Wt,
                       int K, int N) {
    __shared__ float t[32][33];
    int k0 = blockIdx.y * 32, n0 = blockIdx.x * 32;
    int tx = threadIdx.x, ty = threadIdx.y;
#pragma unroll
    for (int r = ty; r < 32; r += 8)
        t[r][tx] = W[(size_t)(k0 + r) * N + n0 + tx];
    __syncthreads();
#pragma unroll
    for (int r = ty; r < 32; r += 8)
        Wt[(size_t)(n0 + r) * K + k0 + tx] = __float2half_rn(t[tx][r]);
}

// ------------------------------ aggregation -------------------------------
// Warp per node. Lane holds U4 uint4 (8 halfs each). fp32 accumulation,
// fp16 output. U4=1 -> F=256, U4=2 -> F=512.

template <int U4>
__global__ void __launch_bounds__(256)
k_agg_h(const uint4* __restrict__ X, uint4* __restrict__ Y,
        const int* __restrict__ rowptr, const int* __restrict__ colidx,
        const float* __restrict__ epsp, int n) {
    int warp = (blockIdx.x * blockDim.x + threadIdx.x) >> 5;
    if (warp >= n) return;
    int lane = threadIdx.x & 31;
    float sc = 1.0f + epsp[0];
    const int rowU = 32 * U4;
    size_t base = (size_t)warp * rowU + lane;

    float acc[U4][8];
#pragma unroll
    for (int u = 0; u < U4; u++) {
        uint4 v = __ldg(&X[base + u * 32]);
        const __half2* hp = (const __half2*)&v;
#pragma unroll
        for (int q = 0; q < 4; q++) {
            float2 f = __half22float2(hp[q]);
            acc[u][2 * q] = sc * f.x;
            acc[u][2 * q + 1] = sc * f.y;
        }
    }

    int beg = rowptr[warp];
    int end = rowptr[warp + 1];
    int j = beg;
    for (; j + 1 < end; j += 2) {
        int r0 = __ldg(&colidx[j]);
        int r1 = __ldg(&colidx[j + 1]);
#pragma unroll
        for (int u = 0; u < U4; u++) {
            uint4 v0 = __ldg(&X[(size_t)r0 * rowU + lane + u * 32]);
            uint4 v1 = __ldg(&X[(size_t)r1 * rowU + lane + u * 32]);
            const __half2* h0 = (const __half2*)&v0;
            const __half2* h1 = (const __half2*)&v1;
#pragma unroll
            for (int q = 0; q < 4; q++) {
                float2 f0 = __half22float2(h0[q]);
                float2 f1 = __half22float2(h1[q]);
                acc[u][2 * q] += f0.x + f1.x;
                acc[u][2 * q + 1] += f0.y + f1.y;
            }
        }
    }
    if (j < end) {
        int r0 = __ldg(&colidx[j]);
#pragma unroll
        for (int u = 0; u < U4; u++) {
            uint4 v0 = __ldg(&X[(size_t)r0 * rowU + lane + u * 32]);
            const __half2* h0 = (const __half2*)&v0;
#pragma unroll
            for (int q = 0; q < 4; q++) {
                float2 f0 = __half22float2(h0[q]);
                acc[u][2 * q] += f0.x;
                acc[u][2 * q + 1] += f0.y;
            }
        }
    }

#pragma unroll
    for (int u = 0; u < U4; u++) {
        uint4 o;
        __half2* op = (__half2*)&o;
#pragma unroll
        for (int q = 0; q < 4; q++)
            op[q] = __floats2half2_rn(acc[u][2 * q], acc[u][2 * q + 1]);
        Y[base + u * 32] = o;
    }
}

// --------------------------- fp16 mma.sync GEMM ----------------------------
// C = act(A[M,K] @ Wt[N,K]^T + bias). BM=BN=128, BK=64, 256 thr = 8 warps,
// warp tile 64x32, mma m16n8k16. 3-stage cp.async, one sync per iteration.
// smem A: [m][k] halfs stride 72; smem B: [n][k] halfs stride 72.

#define STG_B 36864              // bytes per stage (A 18432 + B 18432)
#define GSM_BYTES (3 * STG_B)    // 110592

template <bool RELU, bool OUTH>
__global__ void __launch_bounds__(256)
k_gemm_h(const __half* __restrict__ A, const __half* __restrict__ B,
         const float* __restrict__ bias, void* __restrict__ Cv,
         int M, int K, int N) {
    extern __shared__ __align__(16) char smem[];
    const uint32_t sb = smem_u32(smem);

    const int tid = threadIdx.x;
    const int lane = tid & 31;
    const int w = tid >> 5;
    const int gid = lane >> 2;
    const int tig = lane & 3;
    const int wr = (w >> 2) * 64;
    const int wc = (w & 3) * 32;
    const int blockRow = blockIdx.y * 128;
    const int blockCol = blockIdx.x * 128;
    const int nch = K >> 6;

    float c[4][4][4];
#pragma unroll
    for (int i = 0; i < 4; i++)
#pragma unroll
        for (int j = 0; j < 4; j++)
#pragma unroll
            for (int q = 0; q < 4; q++) c[i][j][q] = 0.0f;

#define ISSUE(ci, bf)                                                          \
    {                                                                          \
        uint32_t pa = sb + (bf) * STG_B;                                       \
        uint32_t pb = pa + 18432;                                              \
        int KT = (ci) << 6;                                                    \
        _Pragma("unroll") for (int t = 0; t < 4; t++) {                        \
            int cidx = tid + t * 256;                                          \
            int row = cidx >> 3, q = cidx & 7;                                 \
            int grow = blockRow + row;                                         \
            cp16(pa + row * 144 + q * 16,                                      \
                 &A[(size_t)grow * K + KT + q * 8], grow < M ? 16 : 0);        \
        }                                                                      \
        _Pragma("unroll") for (int t = 0; t < 4; t++) {                        \
            int cidx = tid + t * 256;                                          \
            int row = cidx >> 3, q = cidx & 7;                                 \
            cp16(pb + row * 144 + q * 16,                                      \
                 &B[(size_t)(blockCol + row) * K + KT + q * 8], 16);           \
        }                                                                      \
        CP_COMMIT();                                                           \
    }

    ISSUE(0, 0);
    if (nch > 1) ISSUE(1, 1);

    for (int i = 0; i < nch; i++) {
        if (i + 2 <= nch) { CP_WAIT(1); } else { CP_WAIT(0); }
        __syncthreads();

        int bf = i % 3;
        const __half* sAh = (const __half*)(smem + bf * STG_B);
        const __half* sBh = (const __half*)(smem + bf * STG_B + 18432);
#pragma unroll
        for (int ks = 0; ks < 4; ks++) {
            int kb = ks * 16;
            uint32_t a[4][4], b[4][2];
#pragma unroll
            for (int ii = 0; ii < 4; ii++) {
                int m0 = wr + ii * 16 + gid;
                a[ii][0] = *(const uint32_t*)&sAh[m0 * 72 + kb + tig * 2];
                a[ii][1] = *(const uint32_t*)&sAh[(m0 + 8) * 72 + kb + tig * 2];
                a[ii][2] = *(const uint32_t*)&sAh[m0 * 72 + kb + tig * 2 + 8];
                a[ii][3] = *(const uint32_t*)&sAh[(m0 + 8) * 72 + kb + tig * 2 + 8];
            }
#pragma unroll
            for (int j = 0; j < 4; j++) {
                int n0 = wc + j * 8 + gid;
                b[j][0] = *(const uint32_t*)&sBh[n0 * 72 + kb + tig * 2];
                b[j][1] = *(const uint32_t*)&sBh[n0 * 72 + kb + tig * 2 + 8];
            }
#pragma unroll
            for (int ii = 0; ii < 4; ii++)
#pragma unroll
                for (int j = 0; j < 4; j++) mma_f16(c[ii][j], a[ii], b[j]);
        }
        if (i + 2 < nch) ISSUE(i + 2, (i + 2) % 3);
    }

    // epilogue
#pragma unroll
    for (int j = 0; j < 4; j++) {
        int n0 = blockCol + wc + j * 8 + 2 * tig;
        float bb0 = bias[n0];
        float bb1 = bias[n0 + 1];
#pragma unroll
        for (int i = 0; i < 4; i++) {
            int m = blockRow + wr + i * 16 + gid;
            float v0 = c[i][j][0] + bb0;
            float v1 = c[i][j][1] + bb1;
            float v2 = c[i][j][2] + bb0;
            float v3 = c[i][j][3] + bb1;
            if (RELU) {
                v0 = fmaxf(v0, 0.f); v1 = fmaxf(v1, 0.f);
                v2 = fmaxf(v2, 0.f); v3 = fmaxf(v3, 0.f);
            }
            if (OUTH) {
                __half2* Ch = (__half2*)Cv;
                if (m < M) Ch[(size_t)m * (N >> 1) + (n0 >> 1)] = __floats2half2_rn(v0, v1);
                if (m + 8 < M)
                    Ch[(size_t)(m + 8) * (N >> 1) + (n0 >> 1)] = __floats2half2_rn(v2, v3);
            } else {
                float* Cf = (float*)Cv;
                if (m < M) *(float2*)&Cf[(size_t)m * N + n0] = make_float2(v0, v1);
                if (m + 8 < M)
                    *(float2*)&Cf[(size_t)(m + 8) * N + n0] = make_float2(v2, v3);
            }
        }
    }
#undef ISSUE
}

// ------------------------------ launcher -----------------------------------

extern "C" void kernel_launch(void* const* d_in, const int* in_sizes, int n_in,
                              void* d_out, int out_size) {
    const float* x    = (const float*)d_in[0];
    const int*   ei   = (const int*)d_in[1];
    const float* W1a  = (const float*)d_in[2];
    const float* b1a  = (const float*)d_in[3];
    const float* W1b  = (const float*)d_in[4];
    const float* b1b  = (const float*)d_in[5];
    const float* W2a  = (const float*)d_in[6];
    const float* b2a  = (const float*)d_in[7];
    const float* W2b  = (const float*)d_in[8];
    const float* b2b  = (const float*)d_in[9];
    const float* eps1 = (const float*)d_in[10];
    const float* eps2 = (const float*)d_in[11];
    float*       out  = (float*)d_out;

    int n = in_sizes[0] / 256;  // 100000 nodes
    int E = in_sizes[1] / 2;    // 1600000 edges

    int *rowptr, *colidx, *cnt, *src, *dst, *bsum;
    __half *xh, *h0, *h1, *h2, *g2, *w1a, *w1b, *w2a, *w2b;
    cudaGetSymbolAddress((void**)&rowptr, g_rowptr);
    cudaGetSymbolAddress((void**)&colidx, g_colidx);
    cudaGetSymbolAddress((void**)&cnt, g_cnt);
    cudaGetSymbolAddress((void**)&src, g_src);
    cudaGetSymbolAddress((void**)&dst, g_dst);
    cudaGetSymbolAddress((void**)&bsum, g_bsum);
    cudaGetSymbolAddress((void**)&xh, g_xh);
    cudaGetSymbolAddress((void**)&h0, g_h0);
    cudaGetSymbolAddress((void**)&h1, g_h1);
    cudaGetSymbolAddress((void**)&h2, g_h2);
    cudaGetSymbolAddress((void**)&g2, g_g2);
    cudaGetSymbolAddress((void**)&w1a, g_w1a);
    cudaGetSymbolAddress((void**)&w1b, g_w1b);
    cudaGetSymbolAddress((void**)&w2a, g_w2a);
    cudaGetSymbolAddress((void**)&w2b, g_w2b);

    cudaFuncSetAttribute(k_gemm_h<true, true>,
                         cudaFuncAttributeMaxDynamicSharedMemorySize, GSM_BYTES);
    cudaFuncSetAttribute(k_gemm_h<false, false>,
                         cudaFuncAttributeMaxDynamicSharedMemorySize, GSM_BYTES);

    int zb = (n + 255) / 256;
    int eb = (E + 255) / 256;
    int nb = (n + 1023) / 1024;

    // conversions
    k_cvt_h<<<(n * 64 + 255) / 256, 256>>>((const float4*)x, (__half2*)xh, n * 64);
    k_wt_h<<<dim3(16, 8), dim3(32, 8)>>>(W1a, w1a, 256, 512);
    k_wt_h<<<dim3(16, 16), dim3(32, 8)>>>(W1b, w1b, 512, 512);
    k_wt_h<<<dim3(16, 16), dim3(32, 8)>>>(W2a, w2a, 512, 512);
    k_wt_h<<<dim3(8, 16), dim3(32, 8)>>>(W2b, w2b, 512, 256);

    // edge decode (dtype-robust) + CSR build
    k_detect<<<1, 256>>>(ei);
    k_zero<<<zb, 256>>>(cnt, n);
    k_decode_count<<<eb, 256>>>(ei, E, n, src, dst, cnt);
    k_bsum<<<nb, 256>>>(cnt, n, bsum);
    k_btop<<<1, 128>>>(bsum, nb, rowptr, n);
    k_scanw<<<nb, 256>>>(cnt, n, bsum, rowptr);
    k_zero<<<zb, 256>>>(cnt, n);
    k_scatter<<<eb, 256>>>(src, dst, E, rowptr, cnt, colidx);

    int mtiles = (n + 127) / 128;
    int ab = (n + 7) / 8;

    // Layer 1
    k_agg_h<1><<<ab, 256>>>((const uint4*)xh, (uint4*)h0, rowptr, colidx, eps1, n);
    dim3 g4(4, mtiles);
    k_gemm_h<true, true><<<g4, 256, GSM_BYTES>>>(h0, w1a, b1a, h1, n, 256, 512);
    k_gemm_h<true, true><<<g4, 256, GSM_BYTES>>>(h1, w1b, b1b, h2, n, 512, 512);

    // Layer 2
    k_agg_h<2><<<ab, 256>>>((const uint4*)h2, (uint4*)g2, rowptr, colidx, eps2, n);
    k_gemm_h<true, true><<<g4, 256, GSM_BYTES>>>(g2, w2a, b2a, h1, n, 512, 512);
    dim3 g2d(2, mtiles);
    k_gemm_h<false, false><<<g2d, 256, GSM_BYTES>>>(h1, w2b, b2b, out, n, 512, 256);
}